// round 1
// baseline (speedup 1.0000x reference)
#include <cuda_runtime.h>
#include <cstddef>

// ---------------------------------------------------------------------------
// CTRNN: out[t] = h_t where h_t = 0.8*h_{t-1} + 0.2*tanh(xproj_t + h_{t-1} @ W_hh^T)
// Strategy:
//   Kernel A: xproj = x @ W_in^T + b_in  written directly into d_out[t,b,n].
//   Kernel B: persistent scan kernel, 128 CTAs, grid barrier per step.
//             Step t reads out[t-1] (h_prev) + out[t] (xproj, own elems only),
//             writes updated h into out[t].  f32x2 packed FMA, k-pair packing.
//   Tail:     hidden = out[T-1] copied to out + T*B*N.
// ---------------------------------------------------------------------------

#define B_DIM 256
#define N_DIM 512
#define I_DIM 128
#define NCTA_SCAN 128

static __device__ unsigned int g_bar;

__global__ void reset_bar_kernel() { g_bar = 0u; }

__device__ __forceinline__ unsigned long long ffma2(unsigned long long a,
                                                    unsigned long long b,
                                                    unsigned long long c) {
    unsigned long long d;
    asm("fma.rn.f32x2 %0, %1, %2, %3;" : "=l"(d) : "l"(a), "l"(b), "l"(c));
    return d;
}
__device__ __forceinline__ float lo32(unsigned long long v) {
    return __uint_as_float((unsigned)(v & 0xffffffffull));
}
__device__ __forceinline__ float hi32(unsigned long long v) {
    return __uint_as_float((unsigned)(v >> 32));
}

// Accurate-enough tanh independent of -use_fast_math: exp-based with Taylor
// fallback for small |x| (abs err < 1e-8 small branch, rel err ~1e-6 big branch).
__device__ __forceinline__ float tanh_acc(float x) {
    float ax = fabsf(x);
    float xx = x * x;
    float small = x - 0.33333334f * x * xx;
    float e = __expf(-2.0f * ax);
    float big = copysignf((1.0f - e) / (1.0f + e), x);
    return (ax < 0.05f) ? small : big;
}

// ---------------------------------------------------------------------------
// Kernel A: xproj GEMM.  C[m,n] = sum_i x[m,i]*W_in[n,i] + b_in[n]
// m = t*B + b (M = T*B rows), K = 128, N = 512.
// CTA tile [32m x 32n], 128 threads, micro-tile 2m x 4n, f32x2 k-pair packing.
// ---------------------------------------------------------------------------
__global__ __launch_bounds__(128) void xproj_kernel(
    const float* __restrict__ x, const float* __restrict__ Win,
    const float* __restrict__ bin, float* __restrict__ out) {
    __shared__ float4 xs[32 * 32];  // 32 m-rows x 32 chunks (128 floats)
    __shared__ float4 ws[32 * 32];  // 32 n-rows x 32 chunks

    const int m0 = blockIdx.y * 32;
    const int n0b = blockIdx.x * 32;
    const int tid = threadIdx.x;

    for (int i = tid; i < 32 * 32; i += 128) {
        int r = i >> 5, c = i & 31;
        xs[r * 32 + (c ^ (r & 7))] =
            *(const float4*)(x + (size_t)(m0 + r) * I_DIM + c * 4);
        ws[r * 32 + (c ^ ((r >> 2) & 7))] =
            *(const float4*)(Win + (size_t)(n0b + r) * I_DIM + c * 4);
    }
    __syncthreads();

    const int nq = tid & 7;        // n quad 0..7
    const int bp = tid >> 3;       // m pair 0..15
    const int r0 = bp * 2, r1 = r0 + 1;
    const int wr0 = nq * 4;
    const ulonglong2* xs2 = (const ulonglong2*)xs;
    const ulonglong2* ws2 = (const ulonglong2*)ws;

    unsigned long long acc[2][4] = {};
#pragma unroll 8
    for (int kc = 0; kc < 32; kc++) {
        ulonglong2 h0 = xs2[r0 * 32 + (kc ^ (r0 & 7))];
        ulonglong2 h1 = xs2[r1 * 32 + (kc ^ (r1 & 7))];
#pragma unroll
        for (int j = 0; j < 4; j++) {
            ulonglong2 w = ws2[(wr0 + j) * 32 + (kc ^ nq)];
            acc[0][j] = ffma2(h0.x, w.x, acc[0][j]);
            acc[1][j] = ffma2(h1.x, w.x, acc[1][j]);
            acc[0][j] = ffma2(h0.y, w.y, acc[0][j]);
            acc[1][j] = ffma2(h1.y, w.y, acc[1][j]);
        }
    }

    const int n0 = n0b + nq * 4;
    float4 bias = *(const float4*)(bin + n0);
#pragma unroll
    for (int e = 0; e < 2; e++) {
        int m = m0 + r0 + e;
        float4 o;
        o.x = lo32(acc[e][0]) + hi32(acc[e][0]) + bias.x;
        o.y = lo32(acc[e][1]) + hi32(acc[e][1]) + bias.y;
        o.z = lo32(acc[e][2]) + hi32(acc[e][2]) + bias.z;
        o.w = lo32(acc[e][3]) + hi32(acc[e][3]) + bias.w;
        *(float4*)(out + (size_t)m * N_DIM + n0) = o;
    }
}

// ---------------------------------------------------------------------------
// Kernel B: persistent scan.  grid = (16 n-tiles, 8 b-tiles) = 128 CTAs,
// 128 threads each, 1 CTA/SM (128KB dyn smem).  Per step:
//   load h_prev[32b x 512] -> smem, [32b x 32n] = h_prev @ W^T tile,
//   leaky tanh update, write out[t], grid barrier.
// ---------------------------------------------------------------------------
__global__ __launch_bounds__(128, 1) void scan_kernel(
    const float* __restrict__ h0, const float* __restrict__ Whh,
    float* __restrict__ out, int T) {
    extern __shared__ float4 smem[];
    float4* ws = smem;              // 32 n-rows x 128 chunks = 64KB
    float4* hs = smem + 32 * 128;   // 32 b-rows x 128 chunks = 64KB

    const int BN = B_DIM * N_DIM;
    const int tid = threadIdx.x;
    const int n_base = blockIdx.x * 32;
    const int b_base = blockIdx.y * 32;
    const unsigned int nct = gridDim.x * gridDim.y;

    // persistent W tile
    for (int i = tid; i < 32 * 128; i += 128) {
        int r = i >> 7, c = i & 127;
        ws[r * 128 + (c ^ ((r >> 2) & 7))] =
            *(const float4*)(Whh + (size_t)(n_base + r) * N_DIM + c * 4);
    }

    const int nq = tid & 7;
    const int bp = tid >> 3;
    const int hr0 = bp * 2, hr1 = hr0 + 1;
    const int wr0 = nq * 4;
    const ulonglong2* ws2 = (const ulonglong2*)ws;
    const ulonglong2* hs2 = (const ulonglong2*)hs;
    const int n0 = n_base + nq * 4;

    for (int t = 0; t < T; t++) {
        const float* src = (t == 0) ? h0 : (out + (size_t)(t - 1) * BN);
        for (int i = tid; i < 32 * 128; i += 128) {
            int r = i >> 7, c = i & 127;
            hs[r * 128 + (c ^ (r & 7))] =
                *(const float4*)(src + (size_t)(b_base + r) * N_DIM + c * 4);
        }
        __syncthreads();

        unsigned long long acc[2][4] = {};
#pragma unroll 4
        for (int kc = 0; kc < 128; kc++) {
            ulonglong2 hv0 = hs2[hr0 * 128 + (kc ^ (hr0 & 7))];
            ulonglong2 hv1 = hs2[hr1 * 128 + (kc ^ (hr1 & 7))];
#pragma unroll
            for (int j = 0; j < 4; j++) {
                ulonglong2 w = ws2[(wr0 + j) * 128 + (kc ^ nq)];
                acc[0][j] = ffma2(hv0.x, w.x, acc[0][j]);
                acc[1][j] = ffma2(hv1.x, w.x, acc[1][j]);
                acc[0][j] = ffma2(hv0.y, w.y, acc[0][j]);
                acc[1][j] = ffma2(hv1.y, w.y, acc[1][j]);
            }
        }

        float* outt = out + (size_t)t * BN;
#pragma unroll
        for (int e = 0; e < 2; e++) {
            int bl = hr0 + e;
            int bg = b_base + bl;
            float4 xp = *(const float4*)(outt + (size_t)bg * N_DIM + n0);
            float4 hp = ((const float4*)hs)[bl * 128 + ((n0 >> 2) ^ (bl & 7))];
            float4 o;
            o.x = 0.8f * hp.x + 0.2f * tanh_acc(xp.x + lo32(acc[e][0]) + hi32(acc[e][0]));
            o.y = 0.8f * hp.y + 0.2f * tanh_acc(xp.y + lo32(acc[e][1]) + hi32(acc[e][1]));
            o.z = 0.8f * hp.z + 0.2f * tanh_acc(xp.z + lo32(acc[e][2]) + hi32(acc[e][2]));
            o.w = 0.8f * hp.w + 0.2f * tanh_acc(xp.w + lo32(acc[e][3]) + hi32(acc[e][3]));
            *(float4*)(outt + (size_t)bg * N_DIM + n0) = o;
        }

        if (t != T - 1) {
            __syncthreads();  // all writes of this CTA issued
            if (tid == 0) {
                __threadfence();
                atomicAdd(&g_bar, 1u);
                unsigned int target = nct * (unsigned)(t + 1);
                while (*((volatile unsigned int*)&g_bar) < target) {}
                __threadfence();
            }
            __syncthreads();
        }
    }
}

// ---------------------------------------------------------------------------

extern "C" void kernel_launch(void* const* d_in, const int* in_sizes, int n_in,
                              void* d_out, int out_size) {
    const float* x   = (const float*)d_in[0];
    const float* h0  = (const float*)d_in[1];
    const float* Win = (const float*)d_in[2];
    const float* bin = (const float*)d_in[3];
    const float* Whh = (const float*)d_in[4];
    float* out = (float*)d_out;

    const int T = in_sizes[0] / (B_DIM * I_DIM);
    const int M = T * B_DIM;

    const int scan_smem = 2 * 32 * 128 * (int)sizeof(float4);  // 128 KB
    cudaFuncSetAttribute(scan_kernel,
                         cudaFuncAttributeMaxDynamicSharedMemorySize, scan_smem);

    reset_bar_kernel<<<1, 1>>>();

    dim3 ga(N_DIM / 32, M / 32);  // (16, 8000): x-major -> 16 CTAs reuse x tile in L2
    xproj_kernel<<<ga, 128>>>(x, Win, bin, out);

    dim3 gb(N_DIM / 32, B_DIM / 32);  // (16, 8) = 128 CTAs
    scan_kernel<<<gb, 128, scan_smem>>>(h0, Whh, out, T);

    long long tbn = (long long)T * B_DIM * N_DIM;
    if ((long long)out_size >= tbn + (long long)B_DIM * N_DIM) {
        cudaMemcpyAsync(out + tbn, out + tbn - (long long)B_DIM * N_DIM,
                        (size_t)B_DIM * N_DIM * sizeof(float),
                        cudaMemcpyDeviceToDevice, 0);
    }
}

// round 2
// speedup vs baseline: 1.5549x; 1.5549x over previous
#include <cuda_runtime.h>
#include <cstddef>

#define B_DIM 256
#define N_DIM 512
#define I_DIM 128

// swizzle: rows 8 apart land on different bank groups
#define SW(r) ((((r) ^ ((r) >> 3))) & 7)

static __device__ unsigned int g_bars[256];  // 8 groups, stride 32 (128B apart)

__global__ void reset_bar_kernel() {
    for (int i = 0; i < 256; i++) g_bars[i] = 0u;
}

__device__ __forceinline__ unsigned long long ffma2(unsigned long long a,
                                                    unsigned long long b,
                                                    unsigned long long c) {
    unsigned long long d;
    asm("fma.rn.f32x2 %0, %1, %2, %3;" : "=l"(d) : "l"(a), "l"(b), "l"(c));
    return d;
}
__device__ __forceinline__ float lo32(unsigned long long v) {
    return __uint_as_float((unsigned)(v & 0xffffffffull));
}
__device__ __forceinline__ float hi32(unsigned long long v) {
    return __uint_as_float((unsigned)(v >> 32));
}

__device__ __forceinline__ float tanh_acc(float x) {
    float ax = fabsf(x);
    float small = x - 0.33333334f * x * x * x;
    float e = __expf(-2.0f * ax);
    float big = copysignf((1.0f - e) / (1.0f + e), x);
    return (ax < 0.05f) ? small : big;
}

__device__ __forceinline__ unsigned smem_u32(const void* p) {
    return (unsigned)__cvta_generic_to_shared(p);
}
__device__ __forceinline__ void cp_async16(unsigned dst, const void* src) {
    asm volatile("cp.async.cg.shared.global [%0], [%1], 16;" ::"r"(dst), "l"(src));
}
#define CP_COMMIT asm volatile("cp.async.commit_group;")
#define CP_WAIT1 asm volatile("cp.async.wait_group 1;")
#define CP_WAIT0 asm volatile("cp.async.wait_group 0;")

#define STORE_TILE(buf, slot) do {                                              \
    float4* _p = (buf) + (slot) * 16; int _s = (slot) & 7;                      \
    _Pragma("unroll") for (int _i = 0; _i < 8; _i++) {                          \
        _p[(_i * 2) ^ _s]     = make_float4(res[_i][0], res[_i][1], res[_i][2], res[_i][3]); \
        _p[(_i * 2 + 1) ^ _s] = make_float4(res[_i][4], res[_i][5], res[_i][6], res[_i][7]); \
    } } while (0)

#define ADD_TILE(buf, slot) do {                                                \
    const float4* _p = (buf) + (slot) * 16; int _s = (slot) & 7;                \
    _Pragma("unroll") for (int _i = 0; _i < 8; _i++) {                          \
        float4 _a = _p[(_i * 2) ^ _s], _b = _p[(_i * 2 + 1) ^ _s];              \
        res[_i][0] += _a.x; res[_i][1] += _a.y; res[_i][2] += _a.z; res[_i][3] += _a.w; \
        res[_i][4] += _b.x; res[_i][5] += _b.y; res[_i][6] += _b.z; res[_i][7] += _b.w; \
    } } while (0)

// ---------------------------------------------------------------------------
// xproj: out[m,n] = sum_i x[m,i]*Win[n,i] + bin[n]
// CTA 64m x 128n, 128 threads, micro 8x8 over full K=128 (1 B/MAC).
// ---------------------------------------------------------------------------
__global__ __launch_bounds__(128, 1) void xproj_kernel(
    const float* __restrict__ x, const float* __restrict__ Win,
    const float* __restrict__ bin, float* __restrict__ out) {
    extern __shared__ float4 sm[];
    float4* xs  = sm;              // [64][32]
    float4* wsx = sm + 64 * 32;    // [128][32]

    const int tid = threadIdx.x;
    const int m0 = blockIdx.y * 64;
    const int n0 = blockIdx.x * 128;

    const unsigned xs_b = smem_u32(xs), ws_b = smem_u32(wsx);
#pragma unroll
    for (int l = 0; l < 16; l++) {
        int i = tid + l * 128, r = i >> 5, c = i & 31;
        cp_async16(xs_b + (unsigned)(r * 32 + (c ^ SW(r))) * 16,
                   x + (size_t)(m0 + r) * I_DIM + c * 4);
    }
#pragma unroll
    for (int l = 0; l < 32; l++) {
        int i = tid + l * 128, r = i >> 5, c = i & 31;
        cp_async16(ws_b + (unsigned)(r * 32 + (c ^ SW(r))) * 16,
                   Win + (size_t)(n0 + r) * I_DIM + c * 4);
    }
    CP_COMMIT;
    CP_WAIT0;
    __syncthreads();

    const int tn = tid & 15, tb = tid >> 4;
    int woff[8], wsw[8], hoff[8], hsw[8];
#pragma unroll
    for (int j = 0; j < 8; j++) {
        int wr = 8 * tn + j, xr = 8 * tb + j;
        woff[j] = wr * 32; wsw[j] = SW(wr);
        hoff[j] = xr * 32; hsw[j] = SW(xr);
    }
    const ulonglong2* ws2 = (const ulonglong2*)wsx;
    const ulonglong2* xs2 = (const ulonglong2*)xs;

    unsigned long long acc[8][8];
#pragma unroll
    for (int i = 0; i < 8; i++)
#pragma unroll
        for (int j = 0; j < 8; j++) acc[i][j] = 0ull;

#pragma unroll 1
    for (int kc = 0; kc < 32; kc++) {
        ulonglong2 wv[8];
#pragma unroll
        for (int j = 0; j < 8; j++) wv[j] = ws2[woff[j] + (kc ^ wsw[j])];
#pragma unroll
        for (int i = 0; i < 8; i++) {
            ulonglong2 hv = xs2[hoff[i] + (kc ^ hsw[i])];
#pragma unroll
            for (int j = 0; j < 8; j++) {
                acc[i][j] = ffma2(hv.x, wv[j].x, acc[i][j]);
                acc[i][j] = ffma2(hv.y, wv[j].y, acc[i][j]);
            }
        }
    }

    float4 b0 = *(const float4*)(bin + n0 + 8 * tn);
    float4 b1 = *(const float4*)(bin + n0 + 8 * tn + 4);
#pragma unroll
    for (int i = 0; i < 8; i++) {
        float* orow = out + (size_t)(m0 + 8 * tb + i) * N_DIM + n0 + 8 * tn;
        float4 o0, o1;
        o0.x = lo32(acc[i][0]) + hi32(acc[i][0]) + b0.x;
        o0.y = lo32(acc[i][1]) + hi32(acc[i][1]) + b0.y;
        o0.z = lo32(acc[i][2]) + hi32(acc[i][2]) + b0.z;
        o0.w = lo32(acc[i][3]) + hi32(acc[i][3]) + b0.w;
        o1.x = lo32(acc[i][4]) + hi32(acc[i][4]) + b1.x;
        o1.y = lo32(acc[i][5]) + hi32(acc[i][5]) + b1.y;
        o1.z = lo32(acc[i][6]) + hi32(acc[i][6]) + b1.z;
        o1.w = lo32(acc[i][7]) + hi32(acc[i][7]) + b1.w;
        *(float4*)orow = o0;
        *(float4*)(orow + 4) = o1;
    }
}

// ---------------------------------------------------------------------------
// scan: persistent, 128 CTAs (16 n-tiles x 8 b-tiles), 128 threads.
// Per thread: 8b x 8n micro-tile over K/8=64 (k-split 8, 1 B/MAC), then a
// 3-round smem reduction, distributed epilogue, per-b-group grid barrier.
// ---------------------------------------------------------------------------
__global__ __launch_bounds__(128, 1) void scan_kernel(
    const float* __restrict__ h0, const float* __restrict__ Whh,
    float* __restrict__ out, int T) {
    extern __shared__ float4 sm[];
    float4* ws   = sm;                       // [32][128] W tile (persistent)
    float4* hs   = sm + 4096;                // [32][128] h_prev tile
    float4* red1 = sm + 8192;                // [64][16]  reduction partials
    float4* red2 = sm + 8192 + 1024;         // [32][8]   reduced preact
    float4* xq   = sm + 8192 + 1024 + 256;   // [32][8]   xproj prefetch

    const int tid = threadIdx.x;
    const int n_base = blockIdx.x * 32;
    const int b_base = blockIdx.y * 32;
    const int nb4 = n_base >> 2;
    const int BN = B_DIM * N_DIM;

    // W tile (loaded once, plain)
#pragma unroll 4
    for (int r = 0; r < 32; r++)
        ws[r * 128 + (tid ^ SW(r))] =
            *(const float4*)(Whh + (size_t)(n_base + r) * N_DIM + tid * 4);

    const int tn = tid & 3, tb = (tid >> 2) & 3, ks = tid >> 4;
    const int ksc = ks * 16;
    const int slot16 = tb * 4 + tn;
    int woff[8], wsw[8], hoff[8], hsw[8];
#pragma unroll
    for (int j = 0; j < 8; j++) {
        int wr = 8 * tn + j, hr = 8 * tb + j;
        woff[j] = wr * 128; wsw[j] = SW(wr);
        hoff[j] = hr * 128; hsw[j] = SW(hr);
    }
    const ulonglong2* ws2 = (const ulonglong2*)ws;
    const ulonglong2* hs2 = (const ulonglong2*)hs;
    const unsigned hs_b = smem_u32(hs), xq_b = smem_u32(xq);
    const int er = tid >> 2, ec = tid & 3;  // epilogue mapping

    for (int t = 0; t < T; t++) {
        float* outt = out + (size_t)t * BN;
        // --- async loads: group A = h_prev tile, group B = xproj prefetch ---
        const float* src = (t == 0) ? h0 : (out + (size_t)(t - 1) * BN);
#pragma unroll
        for (int r = 0; r < 32; r++)
            cp_async16(hs_b + (unsigned)(r * 128 + (tid ^ SW(r))) * 16,
                       src + (size_t)(b_base + r) * N_DIM + tid * 4);
        CP_COMMIT;
#pragma unroll
        for (int l = 0; l < 2; l++) {
            int i = tid + l * 128, r = i >> 3, c = i & 7;
            cp_async16(xq_b + (unsigned)(r * 8 + (c ^ SW(r))) * 16,
                       outt + (size_t)(b_base + r) * N_DIM + n_base + c * 4);
        }
        CP_COMMIT;
        CP_WAIT1;  // h tile landed (xp may still be in flight)
        __syncthreads();

        // --- GEMM partial: 8x8 over this thread's 64-k range ---
        unsigned long long acc[8][8];
#pragma unroll
        for (int i = 0; i < 8; i++)
#pragma unroll
            for (int j = 0; j < 8; j++) acc[i][j] = 0ull;

#pragma unroll 1
        for (int kc = 0; kc < 16; kc++) {
            const int col = ksc + kc;
            ulonglong2 wv[8];
#pragma unroll
            for (int j = 0; j < 8; j++) wv[j] = ws2[woff[j] + (col ^ wsw[j])];
#pragma unroll
            for (int i = 0; i < 8; i++) {
                ulonglong2 hv = hs2[hoff[i] + (col ^ hsw[i])];
#pragma unroll
                for (int j = 0; j < 8; j++) {
                    acc[i][j] = ffma2(hv.x, wv[j].x, acc[i][j]);
                    acc[i][j] = ffma2(hv.y, wv[j].y, acc[i][j]);
                }
            }
        }

        float res[8][8];
#pragma unroll
        for (int i = 0; i < 8; i++)
#pragma unroll
            for (int j = 0; j < 8; j++) res[i][j] = lo32(acc[i][j]) + hi32(acc[i][j]);

        // --- reduction over 8 k-splits: 8 -> 4 -> 2 -> 1 ---
        if (ks >= 4) STORE_TILE(red1, (ks - 4) * 16 + slot16);
        __syncthreads();
        if (ks < 4) ADD_TILE(red1, ks * 16 + slot16);
        __syncthreads();
        if (ks == 2 || ks == 3) STORE_TILE(red1, (ks - 2) * 16 + slot16);
        __syncthreads();
        if (ks < 2) ADD_TILE(red1, ks * 16 + slot16);
        __syncthreads();
        if (ks == 1) STORE_TILE(red1, slot16);
        __syncthreads();
        if (ks == 0) {
            ADD_TILE(red1, slot16);
#pragma unroll
            for (int i = 0; i < 8; i++) {
                int row = 8 * tb + i, s = SW(row);
                red2[row * 8 + ((2 * tn) ^ s)] =
                    make_float4(res[i][0], res[i][1], res[i][2], res[i][3]);
                red2[row * 8 + ((2 * tn + 1) ^ s)] =
                    make_float4(res[i][4], res[i][5], res[i][6], res[i][7]);
            }
        }
        CP_WAIT0;  // xp prefetch landed
        __syncthreads();

        // --- distributed epilogue: each thread 1 row x 8 cols ---
        {
            float* orow = outt + (size_t)(b_base + er) * N_DIM + n_base;
            const int s = SW(er);
#pragma unroll
            for (int q = 0; q < 2; q++) {
                int c = 2 * ec + q, sc = c ^ s;
                float4 pre = red2[er * 8 + sc];
                float4 xp = xq[er * 8 + sc];
                float4 hp = hs[er * 128 + ((nb4 + c) ^ s)];
                float4 o;
                o.x = 0.8f * hp.x + 0.2f * tanh_acc(pre.x + xp.x);
                o.y = 0.8f * hp.y + 0.2f * tanh_acc(pre.y + xp.y);
                o.z = 0.8f * hp.z + 0.2f * tanh_acc(pre.z + xp.z);
                o.w = 0.8f * hp.w + 0.2f * tanh_acc(pre.w + xp.w);
                *(float4*)(orow + c * 4) = o;
            }
        }

        // --- per-b-group barrier (16 CTAs each) ---
        if (t != T - 1) {
            __threadfence();
            __syncthreads();
            if (tid == 0) {
                unsigned* ctr = &g_bars[blockIdx.y * 32];
                atomicAdd(ctr, 1u);
                unsigned tgt = 16u * (unsigned)(t + 1);
                volatile unsigned* p = (volatile unsigned*)ctr;
                while (*p < tgt) {}
                __threadfence();
            }
            __syncthreads();
        }
    }
}

// ---------------------------------------------------------------------------

extern "C" void kernel_launch(void* const* d_in, const int* in_sizes, int n_in,
                              void* d_out, int out_size) {
    const float* x   = (const float*)d_in[0];
    const float* h0  = (const float*)d_in[1];
    const float* Win = (const float*)d_in[2];
    const float* bin = (const float*)d_in[3];
    const float* Whh = (const float*)d_in[4];
    float* out = (float*)d_out;

    const int T = in_sizes[0] / (B_DIM * I_DIM);
    const int M = T * B_DIM;

    const int xp_smem = (64 * 32 + 128 * 32) * (int)sizeof(float4);           // 96 KB
    const int sc_smem = (4096 + 4096 + 1024 + 256 + 256) * (int)sizeof(float4);  // 152 KB
    cudaFuncSetAttribute(xproj_kernel,
                         cudaFuncAttributeMaxDynamicSharedMemorySize, xp_smem);
    cudaFuncSetAttribute(scan_kernel,
                         cudaFuncAttributeMaxDynamicSharedMemorySize, sc_smem);

    reset_bar_kernel<<<1, 1>>>();

    dim3 ga(N_DIM / 128, M / 64);  // (4, 4000)
    xproj_kernel<<<ga, 128, xp_smem>>>(x, Win, bin, out);

    dim3 gb(N_DIM / 32, B_DIM / 32);  // (16, 8) = 128 CTAs
    scan_kernel<<<gb, 128, sc_smem>>>(h0, Whh, out, T);

    long long tbn = (long long)T * B_DIM * N_DIM;
    if ((long long)out_size >= tbn + (long long)B_DIM * N_DIM) {
        cudaMemcpyAsync(out + tbn, out + tbn - (long long)B_DIM * N_DIM,
                        (size_t)B_DIM * N_DIM * sizeof(float),
                        cudaMemcpyDeviceToDevice, 0);
    }
}

// round 3
// speedup vs baseline: 1.7361x; 1.1165x over previous
#include <cuda_runtime.h>
#include <cstddef>

#define B_DIM 256
#define N_DIM 512
#define I_DIM 128

#define SW(r) ((((r) ^ ((r) >> 3))) & 7)

static __device__ unsigned int g_bars[256];  // 8 groups, stride 32 (128B apart)

__global__ void reset_bar_kernel() {
    for (int i = 0; i < 256; i++) g_bars[i] = 0u;
}

__device__ __forceinline__ unsigned long long ffma2(unsigned long long a,
                                                    unsigned long long b,
                                                    unsigned long long c) {
    unsigned long long d;
    asm("fma.rn.f32x2 %0, %1, %2, %3;" : "=l"(d) : "l"(a), "l"(b), "l"(c));
    return d;
}
__device__ __forceinline__ float lo32(unsigned long long v) {
    return __uint_as_float((unsigned)(v & 0xffffffffull));
}
__device__ __forceinline__ float hi32(unsigned long long v) {
    return __uint_as_float((unsigned)(v >> 32));
}

__device__ __forceinline__ float tanh_acc(float x) {
    float ax = fabsf(x);
    float small = x - 0.33333334f * x * x * x;
    float e = __expf(-2.0f * ax);
    float big = copysignf((1.0f - e) / (1.0f + e), x);
    return (ax < 0.05f) ? small : big;
}

__device__ __forceinline__ unsigned smem_u32(const void* p) {
    return (unsigned)__cvta_generic_to_shared(p);
}
__device__ __forceinline__ void cp_async16(unsigned dst, const void* src) {
    asm volatile("cp.async.cg.shared.global [%0], [%1], 16;" ::"r"(dst), "l"(src));
}
#define CP_COMMIT asm volatile("cp.async.commit_group;")
#define CP_WAIT1 asm volatile("cp.async.wait_group 1;")
#define CP_WAIT0 asm volatile("cp.async.wait_group 0;")

// ---------------------------------------------------------------------------
// xproj: out[m,n] = sum_i x[m,i]*Win[n,i] + bin[n]   (unchanged from R2)
// ---------------------------------------------------------------------------
__global__ __launch_bounds__(128, 1) void xproj_kernel(
    const float* __restrict__ x, const float* __restrict__ Win,
    const float* __restrict__ bin, float* __restrict__ out) {
    extern __shared__ float4 sm[];
    float4* xs  = sm;              // [64][32]
    float4* wsx = sm + 64 * 32;    // [128][32]

    const int tid = threadIdx.x;
    const int m0 = blockIdx.y * 64;
    const int n0 = blockIdx.x * 128;

    const unsigned xs_b = smem_u32(xs), ws_b = smem_u32(wsx);
#pragma unroll
    for (int l = 0; l < 16; l++) {
        int i = tid + l * 128, r = i >> 5, c = i & 31;
        cp_async16(xs_b + (unsigned)(r * 32 + (c ^ SW(r))) * 16,
                   x + (size_t)(m0 + r) * I_DIM + c * 4);
    }
#pragma unroll
    for (int l = 0; l < 32; l++) {
        int i = tid + l * 128, r = i >> 5, c = i & 31;
        cp_async16(ws_b + (unsigned)(r * 32 + (c ^ SW(r))) * 16,
                   Win + (size_t)(n0 + r) * I_DIM + c * 4);
    }
    CP_COMMIT;
    CP_WAIT0;
    __syncthreads();

    const int tn = tid & 15, tb = tid >> 4;
    int woff[8], wsw[8], hoff[8], hsw[8];
#pragma unroll
    for (int j = 0; j < 8; j++) {
        int wr = 8 * tn + j, xr = 8 * tb + j;
        woff[j] = wr * 32; wsw[j] = SW(wr);
        hoff[j] = xr * 32; hsw[j] = SW(xr);
    }
    const ulonglong2* ws2 = (const ulonglong2*)wsx;
    const ulonglong2* xs2 = (const ulonglong2*)xs;

    unsigned long long acc[8][8];
#pragma unroll
    for (int i = 0; i < 8; i++)
#pragma unroll
        for (int j = 0; j < 8; j++) acc[i][j] = 0ull;

#pragma unroll 1
    for (int kc = 0; kc < 32; kc++) {
        ulonglong2 wv[8];
#pragma unroll
        for (int j = 0; j < 8; j++) wv[j] = ws2[woff[j] + (kc ^ wsw[j])];
#pragma unroll
        for (int i = 0; i < 8; i++) {
            ulonglong2 hv = xs2[hoff[i] + (kc ^ hsw[i])];
#pragma unroll
            for (int j = 0; j < 8; j++) {
                acc[i][j] = ffma2(hv.x, wv[j].x, acc[i][j]);
                acc[i][j] = ffma2(hv.y, wv[j].y, acc[i][j]);
            }
        }
    }

    float4 b0 = *(const float4*)(bin + n0 + 8 * tn);
    float4 b1 = *(const float4*)(bin + n0 + 8 * tn + 4);
#pragma unroll
    for (int i = 0; i < 8; i++) {
        float* orow = out + (size_t)(m0 + 8 * tb + i) * N_DIM + n0 + 8 * tn;
        float4 o0, o1;
        o0.x = lo32(acc[i][0]) + hi32(acc[i][0]) + b0.x;
        o0.y = lo32(acc[i][1]) + hi32(acc[i][1]) + b0.y;
        o0.z = lo32(acc[i][2]) + hi32(acc[i][2]) + b0.z;
        o0.w = lo32(acc[i][3]) + hi32(acc[i][3]) + b0.w;
        o1.x = lo32(acc[i][4]) + hi32(acc[i][4]) + b1.x;
        o1.y = lo32(acc[i][5]) + hi32(acc[i][5]) + b1.y;
        o1.z = lo32(acc[i][6]) + hi32(acc[i][6]) + b1.z;
        o1.w = lo32(acc[i][7]) + hi32(acc[i][7]) + b1.w;
        *(float4*)orow = o0;
        *(float4*)(orow + 4) = o1;
    }
}

// ---------------------------------------------------------------------------
// scan: persistent, 128 CTAs (16 n x 8 b), 128 threads.
// Warp w owns k-slice [w*128, w*128+128): loads its own h slice (no sync),
// computes 8b x 4n micro-tile partials, stores to red[w], ONE syncthreads,
// all threads sum 4 partials + epilogue. tid0-only release/acquire barrier.
// ---------------------------------------------------------------------------
__global__ __launch_bounds__(128, 1) void scan_kernel(
    const float* __restrict__ h0, const float* __restrict__ Whh,
    float* __restrict__ out, int T) {
    extern __shared__ float4 sm[];
    float4* ws  = sm;                    // [32][128] W tile (persistent)  64KB
    float4* hs  = sm + 4096;             // [32][128] h_prev tile          64KB
    float4* red = sm + 8192;             // [4][256]  per-warp partials    16KB
    float4* xq  = sm + 8192 + 1024;      // [2][32][8] xproj dbl-buffer     8KB

    const int tid = threadIdx.x;
    const int lane = tid & 31;
    const int ks = tid >> 5;        // warp id = k-slice
    const int tn = lane & 7;        // n quad: w-rows 4*tn..+4
    const int tb = lane >> 3;       // b group: h-rows 8*tb..+8
    const int n_base = blockIdx.x * 32;
    const int b_base = blockIdx.y * 32;
    const int BN = B_DIM * N_DIM;

    // persistent W tile (cooperative, once)
#pragma unroll 4
    for (int r = 0; r < 32; r++)
        ws[r * 128 + (tid ^ SW(r))] =
            *(const float4*)(Whh + (size_t)(n_base + r) * N_DIM + tid * 4);

    int woff[4], wsw[4], hoff[8], hsw[8];
#pragma unroll
    for (int j = 0; j < 4; j++) {
        int wr = 4 * tn + j;
        woff[j] = wr * 128; wsw[j] = SW(wr);
    }
#pragma unroll
    for (int i = 0; i < 8; i++) {
        int hr = 8 * tb + i;
        hoff[i] = hr * 128; hsw[i] = SW(hr);
    }
    const ulonglong2* ws2 = (const ulonglong2*)ws;
    const ulonglong2* hs2 = (const ulonglong2*)hs;
    const unsigned hs_b = smem_u32(hs), xq_b = smem_u32(xq);
    const int ksc = ks * 32;            // base ull2-chunk of this warp's slice
    const int er = tid >> 2, ec = tid & 3;  // epilogue: row er, f4-cols 2ec,2ec+1
    const int esw = SW(er);

    // h-slice cp.async: lane covers col (ksc+lane... ) one f4-col across rows
    int hdst[32];
#pragma unroll
    for (int r = 0; r < 32; r++)
        hdst[r] = r * 128 + ((ksc + lane) ^ SW(r));

    __syncthreads();  // ws ready

    // prologue: prefetch xq for t=0 into buf 0
    {
        float4* xq0 = xq;
#pragma unroll
        for (int l = 0; l < 2; l++) {
            int i = tid + l * 128, r = i >> 3, c = i & 7;
            cp_async16(smem_u32(xq0) + (unsigned)(r * 8 + (c ^ SW(r))) * 16,
                       out + (size_t)(b_base + r) * N_DIM + n_base + c * 4);
        }
        CP_COMMIT;
    }

    for (int t = 0; t < T; t++) {
        float* outt = out + (size_t)t * BN;
        const float* src = (t == 0) ? h0 : (out + (size_t)(t - 1) * BN);

        // epilogue h_prev prefetch into regs (consumed ~4k cycles later)
        float4 hp0 = *(const float4*)(src + (size_t)(b_base + er) * N_DIM +
                                      n_base + 8 * ec);
        float4 hp1 = *(const float4*)(src + (size_t)(b_base + er) * N_DIM +
                                      n_base + 8 * ec + 4);

        // this warp's h k-slice: 32 rows x 128 floats
        {
            const float* s0 = src + (size_t)b_base * N_DIM + ks * 128 + lane * 4;
#pragma unroll
            for (int r = 0; r < 32; r++)
                cp_async16(hs_b + (unsigned)hdst[r] * 16, s0 + (size_t)r * N_DIM);
            CP_COMMIT;
        }
        CP_WAIT0;  // h slice (+ previously committed xq_t) landed

        // prefetch xq for t+1 into other buffer (hidden under GEMM)
        if (t + 1 < T) {
            float4* xqn = xq + ((t + 1) & 1) * 256;
            const float* xsrc = out + (size_t)(t + 1) * BN;
#pragma unroll
            for (int l = 0; l < 2; l++) {
                int i = tid + l * 128, r = i >> 3, c = i & 7;
                cp_async16(smem_u32(xqn) + (unsigned)(r * 8 + (c ^ SW(r))) * 16,
                           xsrc + (size_t)(b_base + r) * N_DIM + n_base + c * 4);
            }
            CP_COMMIT;
        }

        // GEMM partial: 8x4 micro over this warp's 128-k slice (no sync needed)
        unsigned long long acc[8][4];
#pragma unroll
        for (int i = 0; i < 8; i++)
#pragma unroll
            for (int j = 0; j < 4; j++) acc[i][j] = 0ull;

#pragma unroll 4
        for (int kc = 0; kc < 32; kc++) {
            const int col = ksc + kc;
            ulonglong2 wv[4];
#pragma unroll
            for (int j = 0; j < 4; j++) wv[j] = ws2[woff[j] + (col ^ wsw[j])];
#pragma unroll
            for (int i = 0; i < 8; i++) {
                ulonglong2 hv = hs2[hoff[i] + (col ^ hsw[i])];
#pragma unroll
                for (int j = 0; j < 4; j++) {
                    acc[i][j] = ffma2(hv.x, wv[j].x, acc[i][j]);
                    acc[i][j] = ffma2(hv.y, wv[j].y, acc[i][j]);
                }
            }
        }

        // store partials: red[ks][i][tb][tn] (conflict-free f4 stores)
        {
            float4* rp = red + ks * 256 + tb * 8 + tn;
#pragma unroll
            for (int i = 0; i < 8; i++) {
                rp[i * 32] = make_float4(
                    lo32(acc[i][0]) + hi32(acc[i][0]),
                    lo32(acc[i][1]) + hi32(acc[i][1]),
                    lo32(acc[i][2]) + hi32(acc[i][2]),
                    lo32(acc[i][3]) + hi32(acc[i][3]));
            }
        }
        __syncthreads();  // the ONLY intra-step sync before the barrier

        // epilogue: thread -> row er, f4-cols {2ec, 2ec+1}
        {
            const float4* xqc = xq + (t & 1) * 256;
            const int rbase = (er & 7) * 32 + (er >> 3) * 8;
            float* orow = outt + (size_t)(b_base + er) * N_DIM + n_base;
#pragma unroll
            for (int q = 0; q < 2; q++) {
                int c4 = 2 * ec + q;
                float4 p0 = red[rbase + c4];
                float4 p1 = red[256 + rbase + c4];
                float4 p2 = red[512 + rbase + c4];
                float4 p3 = red[768 + rbase + c4];
                float4 xp = xqc[er * 8 + (c4 ^ esw)];
                float4 hp = q ? hp1 : hp0;
                float4 o;
                o.x = 0.8f * hp.x +
                      0.2f * tanh_acc(p0.x + p1.x + p2.x + p3.x + xp.x);
                o.y = 0.8f * hp.y +
                      0.2f * tanh_acc(p0.y + p1.y + p2.y + p3.y + xp.y);
                o.z = 0.8f * hp.z +
                      0.2f * tanh_acc(p0.z + p1.z + p2.z + p3.z + xp.z);
                o.w = 0.8f * hp.w +
                      0.2f * tanh_acc(p0.w + p1.w + p2.w + p3.w + xp.w);
                *(float4*)(orow + c4 * 4) = o;
            }
        }

        // inter-CTA barrier within b-group (16 CTAs), release/acquire
        if (t != T - 1) {
            __syncthreads();
            if (tid == 0) {
                unsigned int* ctr = &g_bars[blockIdx.y * 32];
                asm volatile("red.release.gpu.global.add.u32 [%0], %1;" ::
                                 "l"(ctr), "r"(1u) : "memory");
                unsigned tgt = 16u * (unsigned)(t + 1), v;
                do {
                    asm volatile("ld.acquire.gpu.global.u32 %0, [%1];"
                                 : "=r"(v) : "l"(ctr) : "memory");
                } while (v < tgt);
            }
            __syncthreads();
        }
    }
}

// ---------------------------------------------------------------------------

extern "C" void kernel_launch(void* const* d_in, const int* in_sizes, int n_in,
                              void* d_out, int out_size) {
    const float* x   = (const float*)d_in[0];
    const float* h0  = (const float*)d_in[1];
    const float* Win = (const float*)d_in[2];
    const float* bin = (const float*)d_in[3];
    const float* Whh = (const float*)d_in[4];
    float* out = (float*)d_out;

    const int T = in_sizes[0] / (B_DIM * I_DIM);
    const int M = T * B_DIM;

    const int xp_smem = (64 * 32 + 128 * 32) * (int)sizeof(float4);        // 96 KB
    const int sc_smem = (4096 + 4096 + 1024 + 512) * (int)sizeof(float4);  // 152 KB
    cudaFuncSetAttribute(xproj_kernel,
                         cudaFuncAttributeMaxDynamicSharedMemorySize, xp_smem);
    cudaFuncSetAttribute(scan_kernel,
                         cudaFuncAttributeMaxDynamicSharedMemorySize, sc_smem);

    reset_bar_kernel<<<1, 1>>>();

    dim3 ga(N_DIM / 128, M / 64);  // (4, 4000)
    xproj_kernel<<<ga, 128, xp_smem>>>(x, Win, bin, out);

    dim3 gb(N_DIM / 32, B_DIM / 32);  // (16, 8) = 128 CTAs
    scan_kernel<<<gb, 128, sc_smem>>>(h0, Whh, out, T);

    long long tbn = (long long)T * B_DIM * N_DIM;
    if ((long long)out_size >= tbn + (long long)B_DIM * N_DIM) {
        cudaMemcpyAsync(out + tbn, out + tbn - (long long)B_DIM * N_DIM,
                        (size_t)B_DIM * N_DIM * sizeof(float),
                        cudaMemcpyDeviceToDevice, 0);
    }
}

// round 6
// speedup vs baseline: 1.7615x; 1.0146x over previous
#include <cuda_runtime.h>
#include <cstddef>

#define B_DIM 256
#define N_DIM 512
#define I_DIM 128
#define BT 16  // b rows per scan CTA
#define NT 64  // n cols per scan CTA

#define SW(r) ((((r) ^ ((r) >> 3))) & 7)

static __device__ unsigned int g_bars[512];  // 16 groups, stride 32 (128B)

__global__ void reset_bar_kernel() {
    for (int i = 0; i < 512; i++) g_bars[i] = 0u;
}

__device__ __forceinline__ unsigned long long ffma2(unsigned long long a,
                                                    unsigned long long b,
                                                    unsigned long long c) {
    unsigned long long d;
    asm("fma.rn.f32x2 %0, %1, %2, %3;" : "=l"(d) : "l"(a), "l"(b), "l"(c));
    return d;
}
__device__ __forceinline__ float lo32(unsigned long long v) {
    return __uint_as_float((unsigned)(v & 0xffffffffull));
}
__device__ __forceinline__ float hi32(unsigned long long v) {
    return __uint_as_float((unsigned)(v >> 32));
}

__device__ __forceinline__ float tanh_acc(float x) {
    float ax = fabsf(x);
    float small = x - 0.33333334f * x * x * x;
    float e = __expf(-2.0f * ax);
    float big = copysignf((1.0f - e) / (1.0f + e), x);
    return (ax < 0.05f) ? small : big;
}

__device__ __forceinline__ unsigned smem_u32(const void* p) {
    return (unsigned)__cvta_generic_to_shared(p);
}
__device__ __forceinline__ void cp_async16(unsigned dst, const void* src) {
    asm volatile("cp.async.cg.shared.global [%0], [%1], 16;" ::"r"(dst), "l"(src));
}
#define CP_COMMIT asm volatile("cp.async.commit_group;")
#define CP_WAIT0 asm volatile("cp.async.wait_group 0;")

// ---------------------------------------------------------------------------
// xproj: out[m,n] = sum_i x[m,i]*Win[n,i] + bin[n]
// ---------------------------------------------------------------------------
__global__ __launch_bounds__(128, 1) void xproj_kernel(
    const float* __restrict__ x, const float* __restrict__ Win,
    const float* __restrict__ bin, float* __restrict__ out) {
    extern __shared__ float4 sm[];
    float4* xs  = sm;              // [64][32]
    float4* wsx = sm + 64 * 32;    // [128][32]

    const int tid = threadIdx.x;
    const int m0 = blockIdx.y * 64;
    const int n0 = blockIdx.x * 128;

    const unsigned xs_b = smem_u32(xs), ws_b = smem_u32(wsx);
#pragma unroll
    for (int l = 0; l < 16; l++) {
        int i = tid + l * 128, r = i >> 5, c = i & 31;
        cp_async16(xs_b + (unsigned)(r * 32 + (c ^ SW(r))) * 16,
                   x + (size_t)(m0 + r) * I_DIM + c * 4);
    }
#pragma unroll
    for (int l = 0; l < 32; l++) {
        int i = tid + l * 128, r = i >> 5, c = i & 31;
        cp_async16(ws_b + (unsigned)(r * 32 + (c ^ SW(r))) * 16,
                   Win + (size_t)(n0 + r) * I_DIM + c * 4);
    }
    CP_COMMIT;
    CP_WAIT0;
    __syncthreads();

    const int tn = tid & 15, tb = tid >> 4;
    int woff[8], wsw[8], hoff[8], hsw[8];
#pragma unroll
    for (int j = 0; j < 8; j++) {
        int wr = 8 * tn + j, xr = 8 * tb + j;
        woff[j] = wr * 32; wsw[j] = SW(wr);
        hoff[j] = xr * 32; hsw[j] = SW(xr);
    }
    const ulonglong2* ws2 = (const ulonglong2*)wsx;
    const ulonglong2* xs2 = (const ulonglong2*)xs;

    unsigned long long acc[8][8];
#pragma unroll
    for (int i = 0; i < 8; i++)
#pragma unroll
        for (int j = 0; j < 8; j++) acc[i][j] = 0ull;

#pragma unroll 1
    for (int kc = 0; kc < 32; kc++) {
        ulonglong2 wv[8];
#pragma unroll
        for (int j = 0; j < 8; j++) wv[j] = ws2[woff[j] + (kc ^ wsw[j])];
#pragma unroll
        for (int i = 0; i < 8; i++) {
            ulonglong2 hv = xs2[hoff[i] + (kc ^ hsw[i])];
#pragma unroll
            for (int j = 0; j < 8; j++) {
                acc[i][j] = ffma2(hv.x, wv[j].x, acc[i][j]);
                acc[i][j] = ffma2(hv.y, wv[j].y, acc[i][j]);
            }
        }
    }

    float4 b0 = *(const float4*)(bin + n0 + 8 * tn);
    float4 b1 = *(const float4*)(bin + n0 + 8 * tn + 4);
#pragma unroll
    for (int i = 0; i < 8; i++) {
        float* orow = out + (size_t)(m0 + 8 * tb + i) * N_DIM + n0 + 8 * tn;
        float4 o0, o1;
        o0.x = lo32(acc[i][0]) + hi32(acc[i][0]) + b0.x;
        o0.y = lo32(acc[i][1]) + hi32(acc[i][1]) + b0.y;
        o0.z = lo32(acc[i][2]) + hi32(acc[i][2]) + b0.z;
        o0.w = lo32(acc[i][3]) + hi32(acc[i][3]) + b0.w;
        o1.x = lo32(acc[i][4]) + hi32(acc[i][4]) + b1.x;
        o1.y = lo32(acc[i][5]) + hi32(acc[i][5]) + b1.y;
        o1.z = lo32(acc[i][6]) + hi32(acc[i][6]) + b1.z;
        o1.w = lo32(acc[i][7]) + hi32(acc[i][7]) + b1.w;
        *(float4*)orow = o0;
        *(float4*)(orow + 4) = o1;
    }
}

// ---------------------------------------------------------------------------
// scan: 128 CTAs = (8 n-tiles of 64) x (16 b-tiles of 16), 128 threads.
// Per CTA step: h tile 16x512 (32KB, 8x redundancy chip-wide), W tile
// 64x512 persistent in smem (128KB). Warp ks owns k-slice [ks*128,+128),
// micro 4b x 8n, 1-sync reduction, per-b-group barrier over 8 CTAs.
// ---------------------------------------------------------------------------
__global__ __launch_bounds__(128, 1) void scan_kernel(
    const float* __restrict__ h0, const float* __restrict__ Whh,
    float* __restrict__ out, int T) {
    extern __shared__ float4 sm[];
    float4* ws  = sm;             // [64][128] W tile persistent   128KB
    float4* hs  = sm + 8192;      // [16][128] h_prev tile          32KB
    float4* red = sm + 10240;     // [4][16][16] per-warp partials  16KB
    float4* xq  = sm + 11264;     // [2][16][16] xproj dbl-buffer    8KB

    const int tid = threadIdx.x;
    const int lane = tid & 31;
    const int ks = tid >> 5;   // warp = k-slice
    const int tn = lane & 7;   // 8 n-rows of W (out cols 8tn..8tn+7)
    const int tb = lane >> 3;  // 4 b-rows (4tb..4tb+3)
    const int n_base = blockIdx.x * NT;
    const int b_base = blockIdx.y * BT;
    const int BN = B_DIM * N_DIM;

    // persistent W tile: 64 n-rows x 512 k
    for (int i = tid; i < 64 * 128; i += 128) {
        int r = i >> 7, c = i & 127;
        ws[r * 128 + (c ^ SW(r))] =
            *(const float4*)(Whh + (size_t)(n_base + r) * N_DIM + c * 4);
    }

    int woff[8], wsw[8], hoff[4], hsw[4];
#pragma unroll
    for (int j = 0; j < 8; j++) {
        int wr = 8 * tn + j;
        woff[j] = wr * 128; wsw[j] = SW(wr);
    }
#pragma unroll
    for (int i = 0; i < 4; i++) {
        int hr = 4 * tb + i;
        hoff[i] = hr * 128; hsw[i] = SW(hr);
    }
    const ulonglong2* ws2 = (const ulonglong2*)ws;
    const ulonglong2* hs2 = (const ulonglong2*)hs;
    const unsigned hs_b = smem_u32(hs);
    const int ksc = ks * 32;                // warp's base ull2-chunk
    const int er = tid >> 3, ec = tid & 7;  // epilogue: row er, f4 cols 2ec,2ec+1
    const int esw = er & 7;

    int hdst[BT];
#pragma unroll
    for (int r = 0; r < BT; r++)
        hdst[r] = r * 128 + ((ksc + lane) ^ SW(r));

    __syncthreads();  // ws ready

    // prologue: prefetch xq for t=0 into buf 0
#pragma unroll
    for (int l = 0; l < 2; l++) {
        int i = tid + l * 128, r = i >> 4, c = i & 15;
        cp_async16(smem_u32(xq) + (unsigned)(r * 16 + (c ^ (r & 7))) * 16,
                   out + (size_t)(b_base + r) * N_DIM + n_base + c * 4);
    }
    CP_COMMIT;

    for (int t = 0; t < T; t++) {
        float* outt = out + (size_t)t * BN;
        const float* src = (t == 0) ? h0 : (out + (size_t)(t - 1) * BN);

        // epilogue h_prev prefetch into regs (consumed much later)
        const float* hrow = src + (size_t)(b_base + er) * N_DIM + n_base + 8 * ec;
        float4 hp0 = *(const float4*)hrow;
        float4 hp1 = *(const float4*)(hrow + 4);

        // this warp's h k-slice: 16 rows x 128 floats
        {
            const float* s0 = src + (size_t)b_base * N_DIM + ks * 128 + lane * 4;
#pragma unroll
            for (int r = 0; r < BT; r++)
                cp_async16(hs_b + (unsigned)hdst[r] * 16, s0 + (size_t)r * N_DIM);
            CP_COMMIT;
        }
        CP_WAIT0;  // h slice + xq(t) landed

        // prefetch xq(t+1) into other buffer (hidden under GEMM)
        if (t + 1 < T) {
            float4* xqn = xq + ((t + 1) & 1) * 256;
            const float* xsrc = out + (size_t)(t + 1) * BN;
#pragma unroll
            for (int l = 0; l < 2; l++) {
                int i = tid + l * 128, r = i >> 4, c = i & 15;
                cp_async16(smem_u32(xqn) + (unsigned)(r * 16 + (c ^ (r & 7))) * 16,
                           xsrc + (size_t)(b_base + r) * N_DIM + n_base + c * 4);
            }
            CP_COMMIT;
        }

        // GEMM partial: 4b x 8n micro over this warp's 128-k slice
        unsigned long long acc[4][8];
#pragma unroll
        for (int i = 0; i < 4; i++)
#pragma unroll
            for (int j = 0; j < 8; j++) acc[i][j] = 0ull;

#pragma unroll 4
        for (int kc = 0; kc < 32; kc++) {
            const int col = ksc + kc;
            ulonglong2 wv[8];
#pragma unroll
            for (int j = 0; j < 8; j++) wv[j] = ws2[woff[j] + (col ^ wsw[j])];
#pragma unroll
            for (int i = 0; i < 4; i++) {
                ulonglong2 hv = hs2[hoff[i] + (col ^ hsw[i])];
#pragma unroll
                for (int j = 0; j < 8; j++) {
                    acc[i][j] = ffma2(hv.x, wv[j].x, acc[i][j]);
                    acc[i][j] = ffma2(hv.y, wv[j].y, acc[i][j]);
                }
            }
        }

        // store partials: red[ks][row][col f4] with col ^ (row&7) swizzle
        {
            float4* rp = red + ks * 256;
#pragma unroll
            for (int i = 0; i < 4; i++) {
                int row = 4 * tb + i, s = row & 7;
                rp[row * 16 + ((2 * tn) ^ s)] = make_float4(
                    lo32(acc[i][0]) + hi32(acc[i][0]),
                    lo32(acc[i][1]) + hi32(acc[i][1]),
                    lo32(acc[i][2]) + hi32(acc[i][2]),
                    lo32(acc[i][3]) + hi32(acc[i][3]));
                rp[row * 16 + ((2 * tn + 1) ^ s)] = make_float4(
                    lo32(acc[i][4]) + hi32(acc[i][4]),
                    lo32(acc[i][5]) + hi32(acc[i][5]),
                    lo32(acc[i][6]) + hi32(acc[i][6]),
                    lo32(acc[i][7]) + hi32(acc[i][7]));
            }
        }
        __syncthreads();  // the ONLY intra-step sync before the barrier

        // epilogue: thread -> row er, f4 cols {2ec, 2ec+1}
        {
            const float4* xqc = xq + (t & 1) * 256;
            float* orow = outt + (size_t)(b_base + er) * N_DIM + n_base;
#pragma unroll
            for (int q = 0; q < 2; q++) {
                int sc = er * 16 + ((2 * ec + q) ^ esw);
                float4 p0 = red[sc];
                float4 p1 = red[256 + sc];
                float4 p2 = red[512 + sc];
                float4 p3 = red[768 + sc];
                float4 xp = xqc[sc];
                float4 hp = q ? hp1 : hp0;
                float4 o;
                o.x = 0.8f * hp.x +
                      0.2f * tanh_acc(p0.x + p1.x + p2.x + p3.x + xp.x);
                o.y = 0.8f * hp.y +
                      0.2f * tanh_acc(p0.y + p1.y + p2.y + p3.y + xp.y);
                o.z = 0.8f * hp.z +
                      0.2f * tanh_acc(p0.z + p1.z + p2.z + p3.z + xp.z);
                o.w = 0.8f * hp.w +
                      0.2f * tanh_acc(p0.w + p1.w + p2.w + p3.w + xp.w);
                *(float4*)(orow + (2 * ec + q) * 4) = o;
            }
        }

        // inter-CTA barrier within b-group (8 CTAs), release/acquire
        if (t != T - 1) {
            __syncthreads();
            if (tid == 0) {
                unsigned int* ctr = &g_bars[blockIdx.y * 32];
                asm volatile("red.release.gpu.global.add.u32 [%0], %1;" ::
                                 "l"(ctr), "r"(1u) : "memory");
                unsigned tgt = 8u * (unsigned)(t + 1), v;
                do {
                    asm volatile("ld.acquire.gpu.global.u32 %0, [%1];"
                                 : "=r"(v) : "l"(ctr) : "memory");
                } while (v < tgt);
            }
            __syncthreads();
        }
    }
}

// ---------------------------------------------------------------------------

extern "C" void kernel_launch(void* const* d_in, const int* in_sizes, int n_in,
                              void* d_out, int out_size) {
    const float* x   = (const float*)d_in[0];
    const float* h0  = (const float*)d_in[1];
    const float* Win = (const float*)d_in[2];
    const float* bin = (const float*)d_in[3];
    const float* Whh = (const float*)d_in[4];
    float* out = (float*)d_out;

    const int T = in_sizes[0] / (B_DIM * I_DIM);
    const int M = T * B_DIM;

    const int xp_smem = (64 * 32 + 128 * 32) * (int)sizeof(float4);          // 96 KB
    const int sc_smem = (8192 + 2048 + 1024 + 512) * (int)sizeof(float4);    // 184 KB
    cudaFuncSetAttribute(xproj_kernel,
                         cudaFuncAttributeMaxDynamicSharedMemorySize, xp_smem);
    cudaFuncSetAttribute(scan_kernel,
                         cudaFuncAttributeMaxDynamicSharedMemorySize, sc_smem);

    reset_bar_kernel<<<1, 1>>>();

    dim3 ga(N_DIM / 128, M / 64);  // (4, 4000)
    xproj_kernel<<<ga, 128, xp_smem>>>(x, Win, bin, out);

    dim3 gb(N_DIM / NT, B_DIM / BT);  // (8, 16) = 128 CTAs
    scan_kernel<<<gb, 128, sc_smem>>>(h0, Whh, out, T);

    long long tbn = (long long)T * B_DIM * N_DIM;
    if ((long long)out_size >= tbn + (long long)B_DIM * N_DIM) {
        cudaMemcpyAsync(out + tbn, out + tbn - (long long)B_DIM * N_DIM,
                        (size_t)B_DIM * N_DIM * sizeof(float),
                        cudaMemcpyDeviceToDevice, 0);
    }
}

// round 10
// speedup vs baseline: 3.0128x; 1.7104x over previous
#include <cuda_runtime.h>
#include <cuda_bf16.h>
#include <cstddef>

#define B_DIM 256
#define N_DIM 512
#define I_DIM 128
#define BT 16  // b rows per scan CTA
#define NT 64  // n cols per scan CTA

#define SW(r) ((((r) ^ ((r) >> 3))) & 7)

static __device__ unsigned int g_bars[512];  // 16 groups, stride 32 (128B)
// h carried as bf16 hi/lo, double-buffered by step parity
static __device__ __nv_bfloat16 g_hhi[2][B_DIM * N_DIM];
static __device__ __nv_bfloat16 g_hlo[2][B_DIM * N_DIM];

__global__ void reset_bar_kernel() {
    for (int i = 0; i < 512; i++) g_bars[i] = 0u;
}

__device__ __forceinline__ unsigned long long ffma2(unsigned long long a,
                                                    unsigned long long b,
                                                    unsigned long long c) {
    unsigned long long d;
    asm("fma.rn.f32x2 %0, %1, %2, %3;" : "=l"(d) : "l"(a), "l"(b), "l"(c));
    return d;
}
__device__ __forceinline__ float lo32(unsigned long long v) {
    return __uint_as_float((unsigned)(v & 0xffffffffull));
}
__device__ __forceinline__ float hi32(unsigned long long v) {
    return __uint_as_float((unsigned)(v >> 32));
}

__device__ __forceinline__ float tanh_acc(float x) {
    float ax = fabsf(x);
    float small = x - 0.33333334f * x * x * x;
    float e = __expf(-2.0f * ax);
    float big = copysignf((1.0f - e) / (1.0f + e), x);
    return (ax < 0.05f) ? small : big;
}

__device__ __forceinline__ unsigned smem_u32(const void* p) {
    return (unsigned)__cvta_generic_to_shared(p);
}
__device__ __forceinline__ void cp_async16(unsigned dst, const void* src) {
    asm volatile("cp.async.cg.shared.global [%0], [%1], 16;" ::"r"(dst), "l"(src));
}
#define CP_COMMIT asm volatile("cp.async.commit_group;")
#define CP_WAIT0 asm volatile("cp.async.wait_group 0;")

__device__ __forceinline__ void ldsm_x4(unsigned& r0, unsigned& r1, unsigned& r2,
                                        unsigned& r3, unsigned addr) {
    asm volatile("ldmatrix.sync.aligned.m8n8.x4.shared.b16 {%0,%1,%2,%3}, [%4];"
                 : "=r"(r0), "=r"(r1), "=r"(r2), "=r"(r3) : "r"(addr));
}
__device__ __forceinline__ void mma16816(float* d, const unsigned* a,
                                         unsigned b0, unsigned b1) {
    asm volatile(
        "mma.sync.aligned.m16n8k16.row.col.f32.bf16.bf16.f32 "
        "{%0,%1,%2,%3}, {%4,%5,%6,%7}, {%8,%9}, {%0,%1,%2,%3};"
        : "+f"(d[0]), "+f"(d[1]), "+f"(d[2]), "+f"(d[3])
        : "r"(a[0]), "r"(a[1]), "r"(a[2]), "r"(a[3]), "r"(b0), "r"(b1));
}

// smem byte offsets for scan kernel (rows padded to 520 bf16 / 68 f32)
#define OFF_WHI 0
#define OFF_WLO 66560
#define OFF_HHI 133120
#define OFF_HLO 149760
#define OFF_RED 166400   // float [4][16][68]
#define OFF_XQ  183808   // float [2][16][68]
#define SMEM_SCAN 192512

// ---------------------------------------------------------------------------
// xproj: out[m,n] = sum_i x[m,i]*Win[n,i] + bin[n]  (fp32 FFMA2, unchanged)
// ---------------------------------------------------------------------------
__global__ __launch_bounds__(128, 1) void xproj_kernel(
    const float* __restrict__ x, const float* __restrict__ Win,
    const float* __restrict__ bin, float* __restrict__ out) {
    extern __shared__ float4 sm[];
    float4* xs  = sm;              // [64][32]
    float4* wsx = sm + 64 * 32;    // [128][32]

    const int tid = threadIdx.x;
    const int m0 = blockIdx.y * 64;
    const int n0 = blockIdx.x * 128;

    const unsigned xs_b = smem_u32(xs), ws_b = smem_u32(wsx);
#pragma unroll
    for (int l = 0; l < 16; l++) {
        int i = tid + l * 128, r = i >> 5, c = i & 31;
        cp_async16(xs_b + (unsigned)(r * 32 + (c ^ SW(r))) * 16,
                   x + (size_t)(m0 + r) * I_DIM + c * 4);
    }
#pragma unroll
    for (int l = 0; l < 32; l++) {
        int i = tid + l * 128, r = i >> 5, c = i & 31;
        cp_async16(ws_b + (unsigned)(r * 32 + (c ^ SW(r))) * 16,
                   Win + (size_t)(n0 + r) * I_DIM + c * 4);
    }
    CP_COMMIT;
    CP_WAIT0;
    __syncthreads();

    const int tn = tid & 15, tb = tid >> 4;
    int woff[8], wsw[8], hoff[8], hsw[8];
#pragma unroll
    for (int j = 0; j < 8; j++) {
        int wr = 8 * tn + j, xr = 8 * tb + j;
        woff[j] = wr * 32; wsw[j] = SW(wr);
        hoff[j] = xr * 32; hsw[j] = SW(xr);
    }
    const ulonglong2* ws2 = (const ulonglong2*)wsx;
    const ulonglong2* xs2 = (const ulonglong2*)xs;

    unsigned long long acc[8][8];
#pragma unroll
    for (int i = 0; i < 8; i++)
#pragma unroll
        for (int j = 0; j < 8; j++) acc[i][j] = 0ull;

#pragma unroll 1
    for (int kc = 0; kc < 32; kc++) {
        ulonglong2 wv[8];
#pragma unroll
        for (int j = 0; j < 8; j++) wv[j] = ws2[woff[j] + (kc ^ wsw[j])];
#pragma unroll
        for (int i = 0; i < 8; i++) {
            ulonglong2 hv = xs2[hoff[i] + (kc ^ hsw[i])];
#pragma unroll
            for (int j = 0; j < 8; j++) {
                acc[i][j] = ffma2(hv.x, wv[j].x, acc[i][j]);
                acc[i][j] = ffma2(hv.y, wv[j].y, acc[i][j]);
            }
        }
    }

    float4 b0 = *(const float4*)(bin + n0 + 8 * tn);
    float4 b1 = *(const float4*)(bin + n0 + 8 * tn + 4);
#pragma unroll
    for (int i = 0; i < 8; i++) {
        float* orow = out + (size_t)(m0 + 8 * tb + i) * N_DIM + n0 + 8 * tn;
        float4 o0, o1;
        o0.x = lo32(acc[i][0]) + hi32(acc[i][0]) + b0.x;
        o0.y = lo32(acc[i][1]) + hi32(acc[i][1]) + b0.y;
        o0.z = lo32(acc[i][2]) + hi32(acc[i][2]) + b0.z;
        o0.w = lo32(acc[i][3]) + hi32(acc[i][3]) + b0.w;
        o1.x = lo32(acc[i][4]) + hi32(acc[i][4]) + b1.x;
        o1.y = lo32(acc[i][5]) + hi32(acc[i][5]) + b1.y;
        o1.z = lo32(acc[i][6]) + hi32(acc[i][6]) + b1.z;
        o1.w = lo32(acc[i][7]) + hi32(acc[i][7]) + b1.w;
        *(float4*)orow = o0;
        *(float4*)(orow + 4) = o1;
    }
}

// ---------------------------------------------------------------------------
// scan: 128 CTAs = (8 n-tiles of 64) x (16 b-tiles of 16), 128 threads.
// GEMM via mma.sync m16n8k16 bf16 with hi/lo 3-term split (~fp32 accuracy).
// Warp ks owns k-slice [ks*128,+128). h carried in bf16 hi/lo device scratch,
// written by the epilogue; h_prev for the leaky term lives in registers.
// ---------------------------------------------------------------------------
__global__ __launch_bounds__(128, 1) void scan_kernel(
    const float* __restrict__ h0, const float* __restrict__ Whh,
    float* __restrict__ out, int T) {
    extern __shared__ char smem[];
    __nv_bfloat16* whi = (__nv_bfloat16*)(smem + OFF_WHI);  // [64][520]
    __nv_bfloat16* wlo = (__nv_bfloat16*)(smem + OFF_WLO);  // [64][520]
    __nv_bfloat16* hhi = (__nv_bfloat16*)(smem + OFF_HHI);  // [16][520]
    __nv_bfloat16* hlo = (__nv_bfloat16*)(smem + OFF_HLO);  // [16][520]
    float* red = (float*)(smem + OFF_RED);                  // [4][16][68]
    float* xq  = (float*)(smem + OFF_XQ);                   // [2][16][68]

    const int tid = threadIdx.x;
    const int lane = tid & 31;
    const int ks = tid >> 5;  // warp = k-slice [ks*128, +128)
    const int n_base = blockIdx.x * NT;
    const int b_base = blockIdx.y * BT;
    const int BN = B_DIM * N_DIM;

    // ---- prologue: W -> hi/lo bf16 smem (once) ----
    for (int i = tid; i < 64 * 128; i += 128) {
        int r = i >> 7, c = (i & 127) * 4;
        float4 w = *(const float4*)(Whh + (size_t)(n_base + r) * N_DIM + c);
        __nv_bfloat16 h0b = __float2bfloat16(w.x);
        __nv_bfloat16 h1b = __float2bfloat16(w.y);
        __nv_bfloat16 h2b = __float2bfloat16(w.z);
        __nv_bfloat16 h3b = __float2bfloat16(w.w);
        __nv_bfloat16 l0b = __float2bfloat16(w.x - __bfloat162float(h0b));
        __nv_bfloat16 l1b = __float2bfloat16(w.y - __bfloat162float(h1b));
        __nv_bfloat16 l2b = __float2bfloat16(w.z - __bfloat162float(h2b));
        __nv_bfloat16 l3b = __float2bfloat16(w.w - __bfloat162float(h3b));
        __nv_bfloat16* ph = whi + r * 520 + c;
        __nv_bfloat16* pl = wlo + r * 520 + c;
        ph[0] = h0b; ph[1] = h1b; ph[2] = h2b; ph[3] = h3b;
        pl[0] = l0b; pl[1] = l1b; pl[2] = l2b; pl[3] = l3b;
    }

    // ---- prologue: h0 -> hi/lo device scratch parity 0 (own 16 rows, full k;
    //      redundant across the 8 n-group CTAs but identical bytes) ----
    for (int i = tid; i < BT * 128; i += 128) {
        int r = i >> 7, c = (i & 127) * 4;
        float4 h = *(const float4*)(h0 + (size_t)(b_base + r) * N_DIM + c);
        size_t o = (size_t)(b_base + r) * N_DIM + c;
        __nv_bfloat16 a0 = __float2bfloat16(h.x);
        __nv_bfloat16 a1 = __float2bfloat16(h.y);
        __nv_bfloat16 a2 = __float2bfloat16(h.z);
        __nv_bfloat16 a3 = __float2bfloat16(h.w);
        g_hhi[0][o + 0] = a0;
        g_hhi[0][o + 1] = a1;
        g_hhi[0][o + 2] = a2;
        g_hhi[0][o + 3] = a3;
        g_hlo[0][o + 0] = __float2bfloat16(h.x - __bfloat162float(a0));
        g_hlo[0][o + 1] = __float2bfloat16(h.y - __bfloat162float(a1));
        g_hlo[0][o + 2] = __float2bfloat16(h.z - __bfloat162float(a2));
        g_hlo[0][o + 3] = __float2bfloat16(h.w - __bfloat162float(a3));
    }

    // epilogue ownership: thread -> row er, cols n_base + ec*8 .. +7
    const int er = tid >> 3, ec = tid & 7;
    float hp[8];
    {
        const float* hr = h0 + (size_t)(b_base + er) * N_DIM + n_base + ec * 8;
#pragma unroll
        for (int j = 0; j < 8; j++) hp[j] = hr[j];
    }
    __syncthreads();  // W smem + g_h scratch (block-scope visibility) ready

    // ldmatrix lane addressing (constant per thread)
    const unsigned hhi_u = smem_u32(hhi), hlo_u = smem_u32(hlo);
    const unsigned whi_u = smem_u32(whi), wlo_u = smem_u32(wlo);
    const int ar = lane & 15;                              // A row
    const int acol8 = (lane >> 4) << 3;                    // A k sub-offset
    const int brow0 = (lane & 7) + ((lane >> 4) << 3);     // B row base
    const int bcol8 = lane & 8;                            // B k sub-offset
    const unsigned xq_u = smem_u32(xq);

    // prefetch xq for t=0 (xproj values sitting in out[0])
#pragma unroll
    for (int l = 0; l < 2; l++) {
        int i = tid + l * 128, r = i >> 4, c = i & 15;
        cp_async16(xq_u + (unsigned)(r * 272 + c * 16),
                   out + (size_t)(b_base + r) * N_DIM + n_base + c * 4);
    }
    CP_COMMIT;

    for (int t = 0; t < T; t++) {
        const int p_in = t & 1, p_out = p_in ^ 1;
        float* outt = out + (size_t)t * BN;

        // ---- warp-private h slice load: 16 rows x 128 k, hi+lo ----
        {
            const __nv_bfloat16* ghi = g_hhi[p_in];
            const __nv_bfloat16* glo = g_hlo[p_in];
#pragma unroll
            for (int l = 0; l < 8; l++) {
                int idx = l * 32 + lane;
                int r = idx >> 4, c8 = (idx & 15) * 8;
                unsigned so = (unsigned)((r * 520 + ks * 128 + c8) * 2);
                size_t go = (size_t)(b_base + r) * N_DIM + ks * 128 + c8;
                cp_async16(hhi_u + so, ghi + go);
                cp_async16(hlo_u + so, glo + go);
            }
            CP_COMMIT;
        }
        CP_WAIT0;  // h slice + xq(t) landed (warp-local; no __syncthreads)

        // prefetch xq(t+1) into other buffer (DRAM, hidden under MMA)
        if (t + 1 < T) {
            const float* xsrc = out + (size_t)(t + 1) * BN;
            unsigned xb = xq_u + (unsigned)(((t + 1) & 1) * 16 * 272);
#pragma unroll
            for (int l = 0; l < 2; l++) {
                int i = tid + l * 128, r = i >> 4, c = i & 15;
                cp_async16(xb + (unsigned)(r * 272 + c * 16),
                           xsrc + (size_t)(b_base + r) * N_DIM + n_base + c * 4);
            }
            CP_COMMIT;
        }

        // ---- MMA: D[16 x 64] partial over this warp's 128-k slice ----
        float d[8][4];
#pragma unroll
        for (int nt = 0; nt < 8; nt++)
#pragma unroll
            for (int q = 0; q < 4; q++) d[nt][q] = 0.0f;

#pragma unroll
        for (int kch = 0; kch < 8; kch++) {
            const int kb = ks * 128 + kch * 16;
            unsigned ahi[4], alo[4];
            unsigned aoff = (unsigned)((ar * 520 + kb + acol8) * 2);
            ldsm_x4(ahi[0], ahi[1], ahi[2], ahi[3], hhi_u + aoff);
            ldsm_x4(alo[0], alo[1], alo[2], alo[3], hlo_u + aoff);
#pragma unroll
            for (int np = 0; np < 4; np++) {
                unsigned bh0, bh1, bh2, bh3, bl0, bl1, bl2, bl3;
                unsigned boff =
                    (unsigned)(((np * 16 + brow0) * 520 + kb + bcol8) * 2);
                ldsm_x4(bh0, bh1, bh2, bh3, whi_u + boff);
                ldsm_x4(bl0, bl1, bl2, bl3, wlo_u + boff);
                mma16816(d[2 * np], ahi, bh0, bh1);
                mma16816(d[2 * np], ahi, bl0, bl1);
                mma16816(d[2 * np], alo, bh0, bh1);
                mma16816(d[2 * np + 1], ahi, bh2, bh3);
                mma16816(d[2 * np + 1], ahi, bl2, bl3);
                mma16816(d[2 * np + 1], alo, bh2, bh3);
            }
        }

        // ---- store D partials to red[ks] ----
        {
            float* rp = red + ks * 16 * 68;
            const int g = lane >> 2, tt = (lane & 3) * 2;
#pragma unroll
            for (int nt = 0; nt < 8; nt++) {
                *(float2*)(rp + g * 68 + nt * 8 + tt) =
                    make_float2(d[nt][0], d[nt][1]);
                *(float2*)(rp + (g + 8) * 68 + nt * 8 + tt) =
                    make_float2(d[nt][2], d[nt][3]);
            }
        }
        __syncthreads();

        // ---- epilogue: reduce 4 k-slices + xproj, tanh, leaky, stores ----
        {
            const float* xqc = xq + (t & 1) * 16 * 68;
            const int rb = er * 68 + ec * 8;
            float o[8];
#pragma unroll
            for (int j = 0; j < 8; j++) {
                float pre = red[rb + j] + red[1088 + rb + j] +
                            red[2176 + rb + j] + red[3264 + rb + j] +
                            xqc[er * 68 + ec * 8 + j];
                o[j] = 0.8f * hp[j] + 0.2f * tanh_acc(pre);
                hp[j] = o[j];
            }
            size_t go = (size_t)(b_base + er) * N_DIM + n_base + ec * 8;
            *(float4*)(outt + go) = make_float4(o[0], o[1], o[2], o[3]);
            *(float4*)(outt + go + 4) = make_float4(o[4], o[5], o[6], o[7]);
            // bf16 hi/lo for next step's consumers
            __nv_bfloat16 hi8[8], lo8[8];
#pragma unroll
            for (int j = 0; j < 8; j++) {
                hi8[j] = __float2bfloat16(o[j]);
                lo8[j] = __float2bfloat16(o[j] - __bfloat162float(hi8[j]));
            }
            *(uint4*)(&g_hhi[p_out][go]) = *(uint4*)hi8;
            *(uint4*)(&g_hlo[p_out][go]) = *(uint4*)lo8;
        }

        // ---- inter-CTA barrier within b-group (8 CTAs) ----
        if (t != T - 1) {
            __syncthreads();
            if (tid == 0) {
                unsigned int* ctr = &g_bars[blockIdx.y * 32];
                asm volatile("red.release.gpu.global.add.u32 [%0], %1;" ::
                                 "l"(ctr), "r"(1u) : "memory");
                unsigned tgt = 8u * (unsigned)(t + 1), v;
                do {
                    asm volatile("ld.acquire.gpu.global.u32 %0, [%1];"
                                 : "=r"(v) : "l"(ctr) : "memory");
                } while (v < tgt);
            }
            __syncthreads();
        }
    }
}

// ---------------------------------------------------------------------------

extern "C" void kernel_launch(void* const* d_in, const int* in_sizes, int n_in,
                              void* d_out, int out_size) {
    const float* x   = (const float*)d_in[0];
    const float* h0  = (const float*)d_in[1];
    const float* Win = (const float*)d_in[2];
    const float* bin = (const float*)d_in[3];
    const float* Whh = (const float*)d_in[4];
    float* out = (float*)d_out;

    const int T = in_sizes[0] / (B_DIM * I_DIM);
    const int M = T * B_DIM;

    const int xp_smem = (64 * 32 + 128 * 32) * (int)sizeof(float4);  // 96 KB
    cudaFuncSetAttribute(xproj_kernel,
                         cudaFuncAttributeMaxDynamicSharedMemorySize, xp_smem);
    cudaFuncSetAttribute(scan_kernel,
                         cudaFuncAttributeMaxDynamicSharedMemorySize, SMEM_SCAN);

    reset_bar_kernel<<<1, 1>>>();

    dim3 ga(N_DIM / 128, M / 64);  // (4, 4000)
    xproj_kernel<<<ga, 128, xp_smem>>>(x, Win, bin, out);

    dim3 gb(N_DIM / NT, B_DIM / BT);  // (8, 16) = 128 CTAs
    scan_kernel<<<gb, 128, SMEM_SCAN>>>(h0, Whh, out, T);

    long long tbn = (long long)T * B_DIM * N_DIM;
    if ((long long)out_size >= tbn + (long long)B_DIM * N_DIM) {
        cudaMemcpyAsync(out + tbn, out + tbn - (long long)B_DIM * N_DIM,
                        (size_t)B_DIM * N_DIM * sizeof(float),
                        cudaMemcpyDeviceToDevice, 0);
    }
}

// round 11
// speedup vs baseline: 3.4949x; 1.1600x over previous
#include <cuda_runtime.h>
#include <cuda_bf16.h>
#include <cstddef>

#define B_DIM 256
#define N_DIM 512
#define I_DIM 128
#define BT 16  // b rows per scan CTA
#define NT 64  // n cols per scan CTA

static __device__ unsigned int g_bars[512];  // 16 groups, stride 32 (128B)
// h carried as bf16 hi/lo, double-buffered by step parity
static __device__ __nv_bfloat16 g_hhi[2][B_DIM * N_DIM];
static __device__ __nv_bfloat16 g_hlo[2][B_DIM * N_DIM];

__global__ void reset_bar_kernel() {
    for (int i = 0; i < 512; i++) g_bars[i] = 0u;
}

__device__ __forceinline__ float tanh_acc(float x) {
    float ax = fabsf(x);
    float small = x - 0.33333334f * x * x * x;
    float e = __expf(-2.0f * ax);
    float big = copysignf(1.0f - __fdividef(2.0f * e, 1.0f + e), x);
    return (ax < 0.05f) ? small : big;
}

__device__ __forceinline__ unsigned smem_u32(const void* p) {
    return (unsigned)__cvta_generic_to_shared(p);
}
__device__ __forceinline__ void cp_async16(unsigned dst, const void* src) {
    asm volatile("cp.async.cg.shared.global [%0], [%1], 16;" ::"r"(dst), "l"(src));
}
#define CP_COMMIT asm volatile("cp.async.commit_group;")
#define CP_WAIT1 asm volatile("cp.async.wait_group 1;")
#define CP_WAIT0 asm volatile("cp.async.wait_group 0;")

__device__ __forceinline__ void ldsm_x4(unsigned& r0, unsigned& r1, unsigned& r2,
                                        unsigned& r3, unsigned addr) {
    asm volatile("ldmatrix.sync.aligned.m8n8.x4.shared.b16 {%0,%1,%2,%3}, [%4];"
                 : "=r"(r0), "=r"(r1), "=r"(r2), "=r"(r3) : "r"(addr));
}
__device__ __forceinline__ void mma16816(float* d, const unsigned* a,
                                         unsigned b0, unsigned b1) {
    asm volatile(
        "mma.sync.aligned.m16n8k16.row.col.f32.bf16.bf16.f32 "
        "{%0,%1,%2,%3}, {%4,%5,%6,%7}, {%8,%9}, {%0,%1,%2,%3};"
        : "+f"(d[0]), "+f"(d[1]), "+f"(d[2]), "+f"(d[3])
        : "r"(a[0]), "r"(a[1]), "r"(a[2]), "r"(a[3]), "r"(b0), "r"(b1));
}
__device__ __forceinline__ unsigned pack_bf2(__nv_bfloat16 a, __nv_bfloat16 b) {
    return (unsigned)__bfloat16_as_ushort(a) |
           ((unsigned)__bfloat16_as_ushort(b) << 16);
}

// ---------------------------------------------------------------------------
// xproj via bf16 3-term MMA: out[m,n] = x[m,:]·Win[n,:] + bin[n]
// CTA: 128m x 64n, 128 threads, 2 CTAs/SM. Rows padded to 136 bf16 (272 B).
// ---------------------------------------------------------------------------
#define XP_XHI 0
#define XP_XLO 34816
#define XP_WHI 69632
#define XP_WLO 87040
#define XP_SMEM 104448

__global__ __launch_bounds__(128, 2) void xproj_kernel(
    const float* __restrict__ x, const float* __restrict__ Win,
    const float* __restrict__ bin, float* __restrict__ out) {
    extern __shared__ char smem[];
    __nv_bfloat16* xhi = (__nv_bfloat16*)(smem + XP_XHI);  // [128][136]
    __nv_bfloat16* xlo = (__nv_bfloat16*)(smem + XP_XLO);
    __nv_bfloat16* whi = (__nv_bfloat16*)(smem + XP_WHI);  // [64][136]
    __nv_bfloat16* wlo = (__nv_bfloat16*)(smem + XP_WLO);

    const int tid = threadIdx.x;
    const int lane = tid & 31;
    const int w = tid >> 5;
    const int m0 = blockIdx.y * 128;
    const int n0 = blockIdx.x * 64;

    // load + split x tile [128][128]
#pragma unroll 4
    for (int l = 0; l < 32; l++) {
        int i = tid + l * 128, r = i >> 5, c4 = (i & 31) * 4;
        float4 v = *(const float4*)(x + (size_t)(m0 + r) * I_DIM + c4);
        __nv_bfloat16 h0 = __float2bfloat16(v.x), h1 = __float2bfloat16(v.y);
        __nv_bfloat16 h2 = __float2bfloat16(v.z), h3 = __float2bfloat16(v.w);
        uint2 uh = make_uint2(pack_bf2(h0, h1), pack_bf2(h2, h3));
        uint2 ul = make_uint2(
            pack_bf2(__float2bfloat16(v.x - __bfloat162float(h0)),
                     __float2bfloat16(v.y - __bfloat162float(h1))),
            pack_bf2(__float2bfloat16(v.z - __bfloat162float(h2)),
                     __float2bfloat16(v.w - __bfloat162float(h3))));
        *(uint2*)(xhi + r * 136 + c4) = uh;
        *(uint2*)(xlo + r * 136 + c4) = ul;
    }
    // load + split W tile [64][128]
#pragma unroll 4
    for (int l = 0; l < 16; l++) {
        int i = tid + l * 128, r = i >> 5, c4 = (i & 31) * 4;
        float4 v = *(const float4*)(Win + (size_t)(n0 + r) * I_DIM + c4);
        __nv_bfloat16 h0 = __float2bfloat16(v.x), h1 = __float2bfloat16(v.y);
        __nv_bfloat16 h2 = __float2bfloat16(v.z), h3 = __float2bfloat16(v.w);
        uint2 uh = make_uint2(pack_bf2(h0, h1), pack_bf2(h2, h3));
        uint2 ul = make_uint2(
            pack_bf2(__float2bfloat16(v.x - __bfloat162float(h0)),
                     __float2bfloat16(v.y - __bfloat162float(h1))),
            pack_bf2(__float2bfloat16(v.z - __bfloat162float(h2)),
                     __float2bfloat16(v.w - __bfloat162float(h3))));
        *(uint2*)(whi + r * 136 + c4) = uh;
        *(uint2*)(wlo + r * 136 + c4) = ul;
    }
    __syncthreads();

    const unsigned xhi_u = smem_u32(xhi), xlo_u = smem_u32(xlo);
    const unsigned whi_u = smem_u32(whi), wlo_u = smem_u32(wlo);
    const int ar = lane & 15, acol8 = (lane >> 4) << 3;
    const int brow0 = (lane & 7) + ((lane >> 4) << 3), bcol8 = lane & 8;
    const int mbase = 32 * w;

    float d[2][8][4];
#pragma unroll
    for (int mt = 0; mt < 2; mt++)
#pragma unroll
        for (int nt = 0; nt < 8; nt++)
#pragma unroll
            for (int q = 0; q < 4; q++) d[mt][nt][q] = 0.0f;

#pragma unroll
    for (int kch = 0; kch < 8; kch++) {
        const int kb = kch * 16;
        unsigned ahi[2][4], alo[2][4];
#pragma unroll
        for (int mt = 0; mt < 2; mt++) {
            unsigned aoff =
                (unsigned)(((mbase + 16 * mt + ar) * 136 + kb + acol8) * 2);
            ldsm_x4(ahi[mt][0], ahi[mt][1], ahi[mt][2], ahi[mt][3], xhi_u + aoff);
            ldsm_x4(alo[mt][0], alo[mt][1], alo[mt][2], alo[mt][3], xlo_u + aoff);
        }
#pragma unroll
        for (int np = 0; np < 4; np++) {
            unsigned bh0, bh1, bh2, bh3, bl0, bl1, bl2, bl3;
            unsigned boff =
                (unsigned)(((np * 16 + brow0) * 136 + kb + bcol8) * 2);
            ldsm_x4(bh0, bh1, bh2, bh3, whi_u + boff);
            ldsm_x4(bl0, bl1, bl2, bl3, wlo_u + boff);
#pragma unroll
            for (int mt = 0; mt < 2; mt++) {
                mma16816(d[mt][2 * np], ahi[mt], bh0, bh1);
                mma16816(d[mt][2 * np], ahi[mt], bl0, bl1);
                mma16816(d[mt][2 * np], alo[mt], bh0, bh1);
                mma16816(d[mt][2 * np + 1], ahi[mt], bh2, bh3);
                mma16816(d[mt][2 * np + 1], ahi[mt], bl2, bl3);
                mma16816(d[mt][2 * np + 1], alo[mt], bh2, bh3);
            }
        }
    }

    // epilogue: bias + fp32 stores (float2 per row fragment)
    const int g = lane >> 2, tt = (lane & 3) * 2;
#pragma unroll
    for (int nt = 0; nt < 8; nt++) {
        float2 bias2 = *(const float2*)(bin + n0 + nt * 8 + tt);
#pragma unroll
        for (int mt = 0; mt < 2; mt++) {
#pragma unroll
            for (int rr = 0; rr < 2; rr++) {
                int row = m0 + mbase + 16 * mt + g + 8 * rr;
                float2 v = make_float2(d[mt][nt][2 * rr] + bias2.x,
                                       d[mt][nt][2 * rr + 1] + bias2.y);
                *(float2*)(out + (size_t)row * N_DIM + n0 + nt * 8 + tt) = v;
            }
        }
    }
}

// smem byte offsets for scan kernel (rows padded to 520 bf16 / 68 f32)
#define OFF_WHI 0
#define OFF_WLO 66560
#define OFF_HHI 133120
#define OFF_HLO 149760
#define OFF_RED 166400   // float [4][16][68]
#define OFF_XQ  183808   // float [2][16][68]
#define SMEM_SCAN 192512

// ---------------------------------------------------------------------------
// scan: 128 CTAs = (8 n-tiles of 64) x (16 b-tiles of 16), 128 threads.
// GEMM via mma.sync m16n8k16 bf16 hi/lo 3-term split, warp-per-k-slice.
// h carried in bf16 hi/lo device scratch; hp in registers.
// ---------------------------------------------------------------------------
__global__ __launch_bounds__(128, 1) void scan_kernel(
    const float* __restrict__ h0, const float* __restrict__ Whh,
    float* __restrict__ out, int T) {
    extern __shared__ char smem[];
    __nv_bfloat16* whi = (__nv_bfloat16*)(smem + OFF_WHI);  // [64][520]
    __nv_bfloat16* wlo = (__nv_bfloat16*)(smem + OFF_WLO);  // [64][520]
    __nv_bfloat16* hhi = (__nv_bfloat16*)(smem + OFF_HHI);  // [16][520]
    __nv_bfloat16* hlo = (__nv_bfloat16*)(smem + OFF_HLO);  // [16][520]
    float* red = (float*)(smem + OFF_RED);                  // [4][16][68]
    float* xq  = (float*)(smem + OFF_XQ);                   // [2][16][68]

    const int tid = threadIdx.x;
    const int lane = tid & 31;
    const int ks = tid >> 5;  // warp = k-slice [ks*128, +128)
    const int n_base = blockIdx.x * NT;
    const int b_base = blockIdx.y * BT;
    const int BN = B_DIM * N_DIM;

    // ---- prologue: W -> hi/lo bf16 smem (once) ----
    for (int i = tid; i < 64 * 128; i += 128) {
        int r = i >> 7, c = (i & 127) * 4;
        float4 wv = *(const float4*)(Whh + (size_t)(n_base + r) * N_DIM + c);
        __nv_bfloat16 h0b = __float2bfloat16(wv.x), h1b = __float2bfloat16(wv.y);
        __nv_bfloat16 h2b = __float2bfloat16(wv.z), h3b = __float2bfloat16(wv.w);
        uint2 uh = make_uint2(pack_bf2(h0b, h1b), pack_bf2(h2b, h3b));
        uint2 ul = make_uint2(
            pack_bf2(__float2bfloat16(wv.x - __bfloat162float(h0b)),
                     __float2bfloat16(wv.y - __bfloat162float(h1b))),
            pack_bf2(__float2bfloat16(wv.z - __bfloat162float(h2b)),
                     __float2bfloat16(wv.w - __bfloat162float(h3b))));
        *(uint2*)(whi + r * 520 + c) = uh;
        *(uint2*)(wlo + r * 520 + c) = ul;
    }

    // ---- prologue: h0 -> hi/lo device scratch parity 0 ----
    for (int i = tid; i < BT * 128; i += 128) {
        int r = i >> 7, c = (i & 127) * 4;
        float4 h = *(const float4*)(h0 + (size_t)(b_base + r) * N_DIM + c);
        size_t o = (size_t)(b_base + r) * N_DIM + c;
        __nv_bfloat16 a0 = __float2bfloat16(h.x), a1 = __float2bfloat16(h.y);
        __nv_bfloat16 a2 = __float2bfloat16(h.z), a3 = __float2bfloat16(h.w);
        *(uint2*)(&g_hhi[0][o]) = make_uint2(pack_bf2(a0, a1), pack_bf2(a2, a3));
        *(uint2*)(&g_hlo[0][o]) = make_uint2(
            pack_bf2(__float2bfloat16(h.x - __bfloat162float(a0)),
                     __float2bfloat16(h.y - __bfloat162float(a1))),
            pack_bf2(__float2bfloat16(h.z - __bfloat162float(a2)),
                     __float2bfloat16(h.w - __bfloat162float(a3))));
    }

    // epilogue ownership: thread -> row er, cols n_base + ec*8 .. +7
    const int er = tid >> 3, ec = tid & 7;
    float hp[8];
    {
        const float* hr = h0 + (size_t)(b_base + er) * N_DIM + n_base + ec * 8;
#pragma unroll
        for (int j = 0; j < 8; j++) hp[j] = hr[j];
    }
    __syncthreads();  // W smem + g_h scratch ready

    const unsigned hhi_u = smem_u32(hhi), hlo_u = smem_u32(hlo);
    const unsigned whi_u = smem_u32(whi), wlo_u = smem_u32(wlo);
    const int ar = lane & 15, acol8 = (lane >> 4) << 3;
    const int brow0 = (lane & 7) + ((lane >> 4) << 3), bcol8 = lane & 8;
    const unsigned xq_u = smem_u32(xq);

    // prefetch xq for t=0 (xproj values in out[0])
#pragma unroll
    for (int l = 0; l < 2; l++) {
        int i = tid + l * 128, r = i >> 4, c = i & 15;
        cp_async16(xq_u + (unsigned)(r * 272 + c * 16),
                   out + (size_t)(b_base + r) * N_DIM + n_base + c * 4);
    }
    CP_COMMIT;

    for (int t = 0; t < T; t++) {
        const int p_in = t & 1, p_out = p_in ^ 1;
        float* outt = out + (size_t)t * BN;

        // ---- warp-private h slice load: 16 rows x 128 k, hi+lo ----
        {
            const __nv_bfloat16* ghi = g_hhi[p_in];
            const __nv_bfloat16* glo = g_hlo[p_in];
#pragma unroll
            for (int l = 0; l < 8; l++) {
                int idx = l * 32 + lane;
                int r = idx >> 4, c8 = (idx & 15) * 8;
                unsigned so = (unsigned)((r * 520 + ks * 128 + c8) * 2);
                size_t go = (size_t)(b_base + r) * N_DIM + ks * 128 + c8;
                cp_async16(hhi_u + so, ghi + go);
                cp_async16(hlo_u + so, glo + go);
            }
            CP_COMMIT;
        }
        // commit xq(t+1) BEFORE the wait; wait_group 1 leaves it in flight
        if (t + 1 < T) {
            const float* xsrc = out + (size_t)(t + 1) * BN;
            unsigned xb = xq_u + (unsigned)(((t + 1) & 1) * 16 * 272);
#pragma unroll
            for (int l = 0; l < 2; l++) {
                int i = tid + l * 128, r = i >> 4, c = i & 15;
                cp_async16(xb + (unsigned)(r * 272 + c * 16),
                           xsrc + (size_t)(b_base + r) * N_DIM + n_base + c * 4);
            }
            CP_COMMIT;
            CP_WAIT1;  // h(t) + xq(t) done; xq(t+1) outstanding
        } else {
            CP_WAIT0;
        }

        // ---- MMA: D[16 x 64] partial over this warp's 128-k slice ----
        float d[8][4];
#pragma unroll
        for (int nt = 0; nt < 8; nt++)
#pragma unroll
            for (int q = 0; q < 4; q++) d[nt][q] = 0.0f;

#pragma unroll
        for (int kch = 0; kch < 8; kch++) {
            const int kb = ks * 128 + kch * 16;
            unsigned ahi[4], alo[4];
            unsigned aoff = (unsigned)((ar * 520 + kb + acol8) * 2);
            ldsm_x4(ahi[0], ahi[1], ahi[2], ahi[3], hhi_u + aoff);
            ldsm_x4(alo[0], alo[1], alo[2], alo[3], hlo_u + aoff);
#pragma unroll
            for (int np = 0; np < 4; np++) {
                unsigned bh0, bh1, bh2, bh3, bl0, bl1, bl2, bl3;
                unsigned boff =
                    (unsigned)(((np * 16 + brow0) * 520 + kb + bcol8) * 2);
                ldsm_x4(bh0, bh1, bh2, bh3, whi_u + boff);
                ldsm_x4(bl0, bl1, bl2, bl3, wlo_u + boff);
                mma16816(d[2 * np], ahi, bh0, bh1);
                mma16816(d[2 * np], ahi, bl0, bl1);
                mma16816(d[2 * np], alo, bh0, bh1);
                mma16816(d[2 * np + 1], ahi, bh2, bh3);
                mma16816(d[2 * np + 1], ahi, bl2, bl3);
                mma16816(d[2 * np + 1], alo, bh2, bh3);
            }
        }

        // ---- store D partials to red[ks] ----
        {
            float* rp = red + ks * 16 * 68;
            const int g = lane >> 2, tt = (lane & 3) * 2;
#pragma unroll
            for (int nt = 0; nt < 8; nt++) {
                *(float2*)(rp + g * 68 + nt * 8 + tt) =
                    make_float2(d[nt][0], d[nt][1]);
                *(float2*)(rp + (g + 8) * 68 + nt * 8 + tt) =
                    make_float2(d[nt][2], d[nt][3]);
            }
        }
        __syncthreads();

        // ---- epilogue: reduce + tanh + leaky; g_h first, out under barrier ----
        float o[8];
        {
            const float* xqc = xq + (t & 1) * 16 * 68;
            const int rb = er * 68 + ec * 8;
#pragma unroll
            for (int j = 0; j < 8; j++) {
                float pre = red[rb + j] + red[1088 + rb + j] +
                            red[2176 + rb + j] + red[3264 + rb + j] +
                            xqc[rb + j];
                o[j] = 0.8f * hp[j] + 0.2f * tanh_acc(pre);
                hp[j] = o[j];
            }
            size_t go = (size_t)(b_base + er) * N_DIM + n_base + ec * 8;
            // bf16 hi/lo state for next step's consumers (written FIRST)
            __nv_bfloat16 hi8[8], lo8[8];
#pragma unroll
            for (int j = 0; j < 8; j++) {
                hi8[j] = __float2bfloat16(o[j]);
                lo8[j] = __float2bfloat16(o[j] - __bfloat162float(hi8[j]));
            }
            *(uint4*)(&g_hhi[p_out][go]) = *(uint4*)hi8;
            *(uint4*)(&g_hlo[p_out][go]) = *(uint4*)lo8;
        }

        if (t != T - 1) {
            __syncthreads();  // all g_h writes issued CTA-wide
            if (tid == 0) {
                unsigned int* ctr = &g_bars[blockIdx.y * 32];
                asm volatile("red.release.gpu.global.add.u32 [%0], %1;" ::
                                 "l"(ctr), "r"(1u) : "memory");
            }
        }

        // fp32 history store overlaps the barrier window (exclusive region)
        {
            size_t go = (size_t)(b_base + er) * N_DIM + n_base + ec * 8;
            *(float4*)(outt + go) = make_float4(o[0], o[1], o[2], o[3]);
            *(float4*)(outt + go + 4) = make_float4(o[4], o[5], o[6], o[7]);
        }

        if (t != T - 1) {
            if (tid == 0) {
                unsigned int* ctr = &g_bars[blockIdx.y * 32];
                unsigned tgt = 8u * (unsigned)(t + 1), v;
                do {
                    asm volatile("ld.acquire.gpu.global.u32 %0, [%1];"
                                 : "=r"(v) : "l"(ctr) : "memory");
                } while (v < tgt);
            }
            __syncthreads();
        }
    }
}

// ---------------------------------------------------------------------------

extern "C" void kernel_launch(void* const* d_in, const int* in_sizes, int n_in,
                              void* d_out, int out_size) {
    const float* x   = (const float*)d_in[0];
    const float* h0  = (const float*)d_in[1];
    const float* Win = (const float*)d_in[2];
    const float* bin = (const float*)d_in[3];
    const float* Whh = (const float*)d_in[4];
    float* out = (float*)d_out;

    const int T = in_sizes[0] / (B_DIM * I_DIM);
    const int M = T * B_DIM;

    cudaFuncSetAttribute(xproj_kernel,
                         cudaFuncAttributeMaxDynamicSharedMemorySize, XP_SMEM);
    cudaFuncSetAttribute(scan_kernel,
                         cudaFuncAttributeMaxDynamicSharedMemorySize, SMEM_SCAN);

    reset_bar_kernel<<<1, 1>>>();

    dim3 ga(N_DIM / 64, M / 128);  // (8, 2000)
    xproj_kernel<<<ga, 128, XP_SMEM>>>(x, Win, bin, out);

    dim3 gb(N_DIM / NT, B_DIM / BT);  // (8, 16) = 128 CTAs
    scan_kernel<<<gb, 128, SMEM_SCAN>>>(h0, Whh, out, T);

    long long tbn = (long long)T * B_DIM * N_DIM;
    if ((long long)out_size >= tbn + (long long)B_DIM * N_DIM) {
        cudaMemcpyAsync(out + tbn, out + tbn - (long long)B_DIM * N_DIM,
                        (size_t)B_DIM * N_DIM * sizeof(float),
                        cudaMemcpyDeviceToDevice, 0);
    }
}